// round 9
// baseline (speedup 1.0000x reference)
#include <cuda_runtime.h>
#include <cuda_bf16.h>

// Problem constants: B=32, T=1024, F=4, C=256, S=256, MAX_DUR=8 (durations <= 7)
#define BQ 32
#define TQ 1024
#define FQ 4
#define CQ 256
#define SQ 256
#define ROW_VEC 256   // one frame row [F=4][C=256] = 1024 floats = 256 float4

// Scratch: packed (start<<16 | cnt) per (b, s). 32 KB.
__device__ unsigned g_seg[BQ][SQ];

// ---------------------------------------------------------------------------
// Kernel 1: per-batch inclusive scan of durations (one block per batch),
// then emit packed clamped segment descriptors: start=min(excl,T),
// end=min(incl,T), word = start<<16 | (end-start).
// Dtype: reference declares int64 but JAX w/o x64 downcasts to int32; detect
// on device via high words (all zero <=> int64; P(false pos)=8^-32).
// ---------------------------------------------------------------------------
__global__ __launch_bounds__(SQ) void scan_kernel(const int* __restrict__ dur_raw) {
    __shared__ int warp_tot[8];
    __shared__ int s_is64;

    const int b    = blockIdx.x;
    const int s    = threadIdx.x;
    const int lane = s & 31;
    const int w    = s >> 5;

    if (s < 32) {
        int v = dur_raw[2 * s + 1];                     // candidate int64 high words
        unsigned m = __ballot_sync(0xffffffffu, v != 0);
        if (s == 0) s_is64 = (m == 0u) ? 1 : 0;
    }
    __syncthreads();

    int d = s_is64 ? dur_raw[(b * SQ + s) * 2]          // low word of LE int64
                   : dur_raw[b * SQ + s];

    int x = d;                                          // inclusive warp scan
    #pragma unroll
    for (int off = 1; off < 32; off <<= 1) {
        int y = __shfl_up_sync(0xffffffffu, x, off);
        if (lane >= off) x += y;
    }
    if (lane == 31) warp_tot[w] = x;
    __syncthreads();

    int base = 0;
    #pragma unroll
    for (int i = 0; i < 8; ++i)
        if (i < w) base += warp_tot[i];

    const int incl  = base + x;
    const int start = min(incl - d, TQ);
    const int end   = min(incl, TQ);
    g_seg[b][s] = ((unsigned)start << 16) | (unsigned)(end - start);
}

// ---------------------------------------------------------------------------
// Kernel 2: one block of 64 threads per (b, s). Thread tid owns output
// float4 #tid (c-group) and reduces all 4 freq bins in registers:
// per frame it loads float4s {f*64 + tid}, f=0..3 — 4 independent LDG.128 —
// and the frame loop is fully unrolled to 8 predicated iterations, giving
// 32 independent LDG.128 in flight per thread. No shared, no barrier.
// Warp coalescing: lanes 0..31 at fixed f hit consecutive float4s.
// ---------------------------------------------------------------------------
__global__ __launch_bounds__(64) void agg_kernel(const float4* __restrict__ e4,
                                                 float4* __restrict__ out4) {
    const int blk = blockIdx.x;
    const int b   = blk >> 8;
    const int s   = blk & (SQ - 1);
    const int tid = threadIdx.x;

    const unsigned seg = g_seg[b][s];
    const int start = (int)(seg >> 16);
    const int cnt   = (int)(seg & 0xFFFFu);

    const float4* p = e4 + (size_t)(b * TQ + start) * ROW_VEC + tid;

    float4 a0 = make_float4(0.f, 0.f, 0.f, 0.f);
    float4 a1 = a0, a2 = a0, a3 = a0;

    #pragma unroll
    for (int t = 0; t < 8; ++t) {
        if (t < cnt) {
            const float4* q = p + t * ROW_VEC;
            float4 v0 = q[0 * 64];
            float4 v1 = q[1 * 64];
            float4 v2 = q[2 * 64];
            float4 v3 = q[3 * 64];
            a0.x += v0.x; a0.y += v0.y; a0.z += v0.z; a0.w += v0.w;
            a1.x += v1.x; a1.y += v1.y; a1.z += v1.z; a1.w += v1.w;
            a2.x += v2.x; a2.y += v2.y; a2.z += v2.z; a2.w += v2.w;
            a3.x += v3.x; a3.y += v3.y; a3.z += v3.z; a3.w += v3.w;
        }
    }

    const float inv = (cnt > 0) ? 1.0f / (float)(cnt * FQ) : 0.0f;
    float4 r;
    r.x = ((a0.x + a1.x) + (a2.x + a3.x)) * inv;
    r.y = ((a0.y + a1.y) + (a2.y + a3.y)) * inv;
    r.z = ((a0.z + a1.z) + (a2.z + a3.z)) * inv;
    r.w = ((a0.w + a1.w) + (a2.w + a3.w)) * inv;
    out4[(size_t)blk * 64 + tid] = r;
}

extern "C" void kernel_launch(void* const* d_in, const int* in_sizes, int n_in,
                              void* d_out, int out_size) {
    const float4* e_src = (const float4*)d_in[0];   // [B, T, F, C] float32
    const int*    d_src = (const int*)d_in[1];      // [B, S] int64-or-int32 (detected)
    float4* out = (float4*)d_out;                   // [B, S, C] float32

    scan_kernel<<<BQ, SQ>>>(d_src);
    agg_kernel<<<BQ * SQ, 64>>>(e_src, out);
}

// round 10
// speedup vs baseline: 1.0531x; 1.0531x over previous
#include <cuda_runtime.h>
#include <cuda_bf16.h>

// Problem constants: B=32, T=1024, F=4, C=256, S=256, MAX_DUR=8 (durations <= 7)
#define BQ 32
#define TQ 1024
#define FQ 4
#define CQ 256
#define SQ 256
#define ROW_VEC 256   // one frame row [F=4][C=256] = 1024 floats = 256 float4

// ---------------------------------------------------------------------------
// Single fused kernel. Grid: 32 batches x 64 blocks = 2048 blocks, 256 thr.
// Phase 1 (all 256 threads): inclusive scan of this batch's 256 durations
// (duration row is ~1-2 KB, re-read by 64 blocks/batch -> L1/L2 hits).
// Phase 2: four 64-thread groups; group tg handles segment s = g*4+tg with
// register-resident freq reduction: per frame 4 independent LDG.128, frame
// loop unrolled to 8 predicated iterations. Coalesced float4 store.
//
// Dtype: reference declares int64 but JAX w/o x64 downcasts to int32; detect
// on device via high words (all zero <=> int64; P(false pos)=8^-32).
// ---------------------------------------------------------------------------
__global__ __launch_bounds__(256) void fused_kernel(const float4* __restrict__ e4,
                                                    const int* __restrict__ dur_raw,
                                                    float4* __restrict__ out4) {
    __shared__ int sh_cum[SQ];
    __shared__ int warp_tot[8];
    __shared__ int s_is64;

    const int blk = blockIdx.x;
    const int b   = blk >> 6;          // 64 blocks per batch
    const int g   = blk & 63;          // segment group within batch
    const int tid = threadIdx.x;
    const int lane32 = tid & 31;
    const int w      = tid >> 5;

    // --- dtype probe (first 32 candidate int64 high words of whole array) ---
    if (tid < 32) {
        int v = dur_raw[2 * tid + 1];
        unsigned m = __ballot_sync(0xffffffffu, v != 0);
        if (tid == 0) s_is64 = (m == 0u) ? 1 : 0;
    }
    __syncthreads();

    // --- phase 1: inclusive scan of batch b's durations (tid = phone id) ---
    int d = s_is64 ? dur_raw[(b * SQ + tid) * 2]    // low word of LE int64
                   : dur_raw[b * SQ + tid];

    int x = d;
    #pragma unroll
    for (int off = 1; off < 32; off <<= 1) {
        int y = __shfl_up_sync(0xffffffffu, x, off);
        if (lane32 >= off) x += y;
    }
    if (lane32 == 31) warp_tot[w] = x;
    __syncthreads();

    int base = 0;
    #pragma unroll
    for (int i = 0; i < 8; ++i)
        if (i < w) base += warp_tot[i];

    sh_cum[tid] = base + x;
    __syncthreads();

    // --- phase 2: group tg handles segment s = g*4 + tg ---
    const int tg   = tid >> 6;         // 0..3
    const int lane = tid & 63;         // c-group within segment
    const int s    = (g << 2) + tg;

    const int incl  = sh_cum[s];
    const int excl  = (s == 0) ? 0 : sh_cum[s - 1];
    const int start = min(excl, TQ);
    const int cnt   = min(incl, TQ) - start;

    const float4* p = e4 + (size_t)(b * TQ + start) * ROW_VEC + lane;

    float4 a0 = make_float4(0.f, 0.f, 0.f, 0.f);
    float4 a1 = a0, a2 = a0, a3 = a0;

    #pragma unroll
    for (int t = 0; t < 8; ++t) {
        if (t < cnt) {
            const float4* q = p + t * ROW_VEC;
            float4 v0 = q[0 * 64];
            float4 v1 = q[1 * 64];
            float4 v2 = q[2 * 64];
            float4 v3 = q[3 * 64];
            a0.x += v0.x; a0.y += v0.y; a0.z += v0.z; a0.w += v0.w;
            a1.x += v1.x; a1.y += v1.y; a1.z += v1.z; a1.w += v1.w;
            a2.x += v2.x; a2.y += v2.y; a2.z += v2.z; a2.w += v2.w;
            a3.x += v3.x; a3.y += v3.y; a3.z += v3.z; a3.w += v3.w;
        }
    }

    const float inv = (cnt > 0) ? 1.0f / (float)(cnt * FQ) : 0.0f;
    float4 r;
    r.x = ((a0.x + a1.x) + (a2.x + a3.x)) * inv;
    r.y = ((a0.y + a1.y) + (a2.y + a3.y)) * inv;
    r.z = ((a0.z + a1.z) + (a2.z + a3.z)) * inv;
    r.w = ((a0.w + a1.w) + (a2.w + a3.w)) * inv;
    out4[((size_t)(b * SQ + s)) * 64 + lane] = r;
}

extern "C" void kernel_launch(void* const* d_in, const int* in_sizes, int n_in,
                              void* d_out, int out_size) {
    const float4* e_src = (const float4*)d_in[0];   // [B, T, F, C] float32
    const int*    d_src = (const int*)d_in[1];      // [B, S] int64-or-int32 (detected)
    float4* out = (float4*)d_out;                   // [B, S, C] float32

    fused_kernel<<<BQ * 64, 256>>>(e_src, d_src, out);
}